// round 5
// baseline (speedup 1.0000x reference)
#include <cuda_runtime.h>
#include <math_constants.h>

#define B_      64
#define C_      256
#define HW_     4096            // floats per plane = 1024 float4
#define NPLANE  16384
#define NCL     8

#define GRID_   256
#define TPB_    256
#define NWARP_  (GRID_ * 8)     // 2048 warps
#define PPW_    (NPLANE / NWARP_)  // 8 planes per warp

// ---------------- scratch (static __device__, no allocation) ----------------
__device__ float g_sum[NPLANE];
__device__ float g_min[NPLANE];
__device__ float g_max[NPLANE];
__device__ float g_scale[NPLANE];
__device__ float g_smin[B_];
__device__ float g_smax[B_];

// grid barrier state: cnt reset by last arriver each use; flag monotonic
__device__ unsigned g_cnt[2];
__device__ unsigned g_flag[2];

__device__ __forceinline__ void grid_sync(int k) {
    __syncthreads();
    if (threadIdx.x == 0) {
        __threadfence();
        unsigned f = *((volatile unsigned*)&g_flag[k]);
        unsigned old = atomicAdd(&g_cnt[k], 1u);
        if (old == GRID_ - 1u) {
            g_cnt[k] = 0u;              // safe: all arrived; untouched until next launch
            __threadfence();
            atomicAdd(&g_flag[k], 1u);  // release
        } else {
            while (*((volatile unsigned*)&g_flag[k]) == f) { }
        }
        __threadfence();
    }
    __syncthreads();
}

__global__ __launch_bounds__(TPB_, 2) void fused_pcq(
    const float* __restrict__ x,
    const float* __restrict__ w1, const float* __restrict__ b1,
    const float* __restrict__ w2, const float* __restrict__ b2,
    const float* __restrict__ act_range,
    const int*   __restrict__ cluster,
    float* __restrict__ out)
{
    const int t    = threadIdx.x;
    const int warp = t >> 5;
    const int lane = t & 31;
    const int gw   = blockIdx.x * 8 + warp;   // 0..2047

    // ================= Phase 1: per-plane sum / min / max ===================
    // chunk pi is read grid-wide at (roughly) time step pi
#pragma unroll
    for (int pi = 0; pi < PPW_; ++pi) {
        const int plane = gw + NWARP_ * pi;
        const float4* xp = reinterpret_cast<const float4*>(x + (size_t)plane * HW_);

        float s = 0.f, mn = CUDART_INF_F, mx = -CUDART_INF_F;
#pragma unroll 8
        for (int i = 0; i < 32; ++i) {       // 32 f4/lane * 32 lanes = 1024 f4
            float4 v = xp[lane + 32 * i];
            s += (v.x + v.y) + (v.z + v.w);
            mn = fminf(mn, fminf(fminf(v.x, v.y), fminf(v.z, v.w)));
            mx = fmaxf(mx, fmaxf(fmaxf(v.x, v.y), fmaxf(v.z, v.w)));
        }
#pragma unroll
        for (int o = 16; o; o >>= 1) {
            s  += __shfl_xor_sync(0xffffffffu, s, o);
            mn  = fminf(mn, __shfl_xor_sync(0xffffffffu, mn, o));
            mx  = fmaxf(mx, __shfl_xor_sync(0xffffffffu, mx, o));
        }
        if (lane == 0) {
            g_sum[plane] = s;
            g_min[plane] = mn;
            g_max[plane] = mx;
        }
    }

    grid_sync(0);

    // ================= Phase 2: SE MLP (blocks 0..63, one sample each) ======
    if (blockIdx.x < B_) {
        const int b = blockIdx.x;
        __shared__ float pooled[C_];
        __shared__ float hbuf[64];

        pooled[t] = g_sum[b * C_ + t] * (1.0f / 4096.0f);
        __syncthreads();

        if (t < 64) {
            float acc = b1[t];
            const float* w1r = w1 + t * C_;
#pragma unroll 8
            for (int c = 0; c < C_; ++c) acc += pooled[c] * w1r[c];
            hbuf[t] = fmaxf(acc, 0.0f);
        }
        __syncthreads();

        float v = b2[t];
        const float* w2r = w2 + t * 64;
#pragma unroll 8
        for (int s = 0; s < 64; ++s) v += hbuf[s] * w2r[s];
        float sc = fminf(fmaxf(v * (1.0f / 6.0f) + 0.5f, 0.0f), 1.0f);
        g_scale[b * C_ + t] = sc;

        float pmn = sc * g_min[b * C_ + t];   // scale >= 0
        float pmx = sc * g_max[b * C_ + t];
#pragma unroll
        for (int o = 16; o; o >>= 1) {
            pmn = fminf(pmn, __shfl_xor_sync(0xffffffffu, pmn, o));
            pmx = fmaxf(pmx, __shfl_xor_sync(0xffffffffu, pmx, o));
        }
        __shared__ float sh_mn[8], sh_mx[8];
        if (lane == 0) { sh_mn[warp] = pmn; sh_mx[warp] = pmx; }
        __syncthreads();
        if (t == 0) {
            float tmn = CUDART_INF_F, tmx = -CUDART_INF_F;
#pragma unroll
            for (int w = 0; w < 8; ++w) {
                tmn = fminf(tmn, sh_mn[w]);
                tmx = fmaxf(tmx, sh_mx[w]);
            }
            g_smin[b] = tmn;
            g_smax[b] = tmx;
        }
    }

    grid_sync(1);

    // ================= Phase 3: cluster ranges (redundant) + fake-quant =====
    __shared__ float cs_s[NCL], cs_z[NCL];
    __shared__ float s_ss[B_], s_zz[B_], s_inv[B_];

    if (t < NCL) {
        float cmin = CUDART_INF_F, cmax = -CUDART_INF_F;
        for (int b = 0; b < B_; ++b) {
            if (cluster[b] == t) {
                cmin = fminf(cmin, g_smin[b]);
                cmax = fmaxf(cmax, g_smax[b]);
            }
        }
        const float SMOOTH = 0.995f, ONE_M = 0.005f;
        float nmin = act_range[2 * t]     * SMOOTH + cmin * ONE_M;
        float nmax = act_range[2 * t + 1] * SMOOTH + cmax * ONE_M;
        float s = (nmax - nmin) * (1.0f / 255.0f);
        cs_s[t] = s;
        cs_z[t] = -rintf(nmin / s);
    }
    __syncthreads();
    if (t < B_) {
        int k = cluster[t];
        s_ss[t]  = cs_s[k];
        s_zz[t]  = cs_z[k];
        s_inv[t] = 1.0f / cs_s[k];
    }
    __syncthreads();

    // reverse chunk order: chunk 7 was read most recently in phase 1 -> L2 hit
#pragma unroll
    for (int pi = PPW_ - 1; pi >= 0; --pi) {
        const int plane = gw + NWARP_ * pi;
        const int b = plane >> 8;
        const float sc  = g_scale[plane];
        const float ssv = s_ss[b];
        const float zzv = s_zz[b];
        const float inv = s_inv[b];

        const float4* xp = reinterpret_cast<const float4*>(x   + (size_t)plane * HW_);
        float4*       op = reinterpret_cast<float4*>      (out + (size_t)plane * HW_);

#pragma unroll 4
        for (int i = 0; i < 32; ++i) {
            float4 v = xp[lane + 32 * i];
            float4 r;
            {
                float o = sc * v.x;
                float q = fminf(fmaxf(rintf(fmaf(o, inv, zzv)), 0.0f), 255.0f);
                r.x = (q - zzv) * ssv;
            }
            {
                float o = sc * v.y;
                float q = fminf(fmaxf(rintf(fmaf(o, inv, zzv)), 0.0f), 255.0f);
                r.y = (q - zzv) * ssv;
            }
            {
                float o = sc * v.z;
                float q = fminf(fmaxf(rintf(fmaf(o, inv, zzv)), 0.0f), 255.0f);
                r.z = (q - zzv) * ssv;
            }
            {
                float o = sc * v.w;
                float q = fminf(fmaxf(rintf(fmaf(o, inv, zzv)), 0.0f), 255.0f);
                r.w = (q - zzv) * ssv;
            }
            __stcs(&op[lane + 32 * i], r);
        }
    }
}

// ---------------- launch ----------------------------------------------------
extern "C" void kernel_launch(void* const* d_in, const int* in_sizes, int n_in,
                              void* d_out, int out_size) {
    const float* x          = (const float*)d_in[0];
    const float* w1         = (const float*)d_in[1];
    const float* b1         = (const float*)d_in[2];
    const float* w2         = (const float*)d_in[3];
    const float* b2         = (const float*)d_in[4];
    const float* act_range  = (const float*)d_in[5];
    const int*   cluster    = (const int*)d_in[6];
    float* out = (float*)d_out;

    fused_pcq<<<GRID_, TPB_>>>(x, w1, b1, w2, b2, act_range, cluster, out);
}